// round 9
// baseline (speedup 1.0000x reference)
#include <cuda_runtime.h>
#include <cuda_bf16.h>
#include <math.h>
#include <stdint.h>

// Batched log(M) for SPD 64x64 matrices, spectrum in [1, 6]:
// degree-8 Chebyshev poly of log in T = (M - 3.5 I)/2.5, PS s=2 (4 matmuls),
// mma.sync m16n8k16 bf16 (HMMA), 2-way bf16 split (truncation), 3-term
// products. 1 matrix/CTA, 128 threads. Traffic-minimized: next-step X
// A-fragments for the warp's own k-half come straight from this step's
// accumulators (C-frag == packed A-frag layout); Y (T2) fragments are
// register-cached across steps 1-3. Ping-pong AC buffers, 1 barrier/step.

constexpr int DEG = 8;
struct Poly { float a[DEG + 1]; };

constexpr int TILE = 8192;           // one 64x64 bf16 tile
constexpr int SMEM_TOT = 6 * TILE;   // Th,Tl | T2h,T2l | ACh,ACl (48KB)

__device__ __forceinline__ uint32_t smem_u32(const void* p) {
    uint32_t a;
    asm("{ .reg .u64 t; cvta.to.shared.u64 t, %1; cvt.u32.u64 %0, t; }"
        : "=r"(a) : "l"(p));
    return a;
}
__device__ __forceinline__ void sts32(uint32_t addr, uint32_t v) {
    asm volatile("st.shared.b32 [%0], %1;" :: "r"(addr), "r"(v));
}
__device__ __forceinline__ uint32_t lds32(uint32_t addr) {
    uint32_t v;
    asm volatile("ld.shared.b32 %0, [%1];" : "=r"(v) : "r"(addr));
    return v;
}
__device__ __forceinline__ uint32_t packbf(float lo, float hi) {
    uint32_t r;
    asm("cvt.rn.bf16x2.f32 %0, %1, %2;" : "=r"(r) : "f"(hi), "f"(lo));
    return r;
}
__device__ __forceinline__ float2 unpackbf(uint32_t u) {
    const __nv_bfloat162 b = *reinterpret_cast<const __nv_bfloat162*>(&u);
    return make_float2(__bfloat162float(b.x), __bfloat162float(b.y));
}
// [x0.hi16 | x1.hi16] -> bf16x2 (truncation split, low half = x0)
__device__ __forceinline__ uint32_t prmt_hi(uint32_t a, uint32_t b) {
    uint32_t r;
    asm("prmt.b32 %0, %1, %2, 0x7632;" : "=r"(r) : "r"(a), "r"(b));
    return r;
}
// split pair into truncated-hi bf16x2 and residual-lo bf16x2
__device__ __forceinline__ void split_pair(float x0, float x1,
                                           uint32_t& h01, uint32_t& l01) {
    const uint32_t u0 = __float_as_uint(x0), u1 = __float_as_uint(x1);
    h01 = prmt_hi(u0, u1);
    const float l0 = x0 - __uint_as_float(u0 & 0xFFFF0000u);
    const float l1 = x1 - __uint_as_float(u1 & 0xFFFF0000u);
    l01 = packbf(l0, l1);
}
__device__ __forceinline__ void ldsm4(uint32_t r[4], uint32_t addr) {
    asm volatile("ldmatrix.sync.aligned.m8n8.x4.shared.b16 {%0,%1,%2,%3}, [%4];"
                 : "=r"(r[0]), "=r"(r[1]), "=r"(r[2]), "=r"(r[3]) : "r"(addr));
}
__device__ __forceinline__ void mma16816(float c[4], const uint32_t a[4],
                                         uint32_t b0, uint32_t b1) {
    asm volatile(
        "mma.sync.aligned.m16n8k16.row.col.f32.bf16.bf16.f32 "
        "{%0,%1,%2,%3}, {%4,%5,%6,%7}, {%8,%9}, {%0,%1,%2,%3};"
        : "+f"(c[0]), "+f"(c[1]), "+f"(c[2]), "+f"(c[3])
        : "r"(a[0]), "r"(a[1]), "r"(a[2]), "r"(a[3]), "r"(b0), "r"(b1));
}

// one k16 chunk: 8 (mi,ni) C tiles x 3 split terms
__device__ __forceinline__ void mma_chunk(float acc[8][4],
                                          const uint32_t ah0[4], const uint32_t al0[4],
                                          const uint32_t ah1[4], const uint32_t al1[4],
                                          const uint32_t bh[2][4], const uint32_t bl[2][4]) {
#pragma unroll
    for (int mi = 0; mi < 2; ++mi) {
        const uint32_t* ah = mi ? ah1 : ah0;
        const uint32_t* al = mi ? al1 : al0;
#pragma unroll
        for (int ni = 0; ni < 4; ++ni) {
            const int nj = ni >> 1, sub = ni & 1;
            float* c = acc[mi * 4 + ni];
            mma16816(c, ah, bh[nj][sub], bh[nj][sub + 2]);  // Ah*Bh
            mma16816(c, ah, bl[nj][sub], bl[nj][sub + 2]);  // Ah*Bl
            mma16816(c, al, bh[nj][sub], bh[nj][sub + 2]);  // Al*Bh
        }
    }
}

__global__ __launch_bounds__(128, 2)
void logm_hmma_kernel(const float* __restrict__ gin,
                      float* __restrict__ gout,
                      Poly P) {
    extern __shared__ char smc[];
    const uint32_t sb  = smem_u32(smc);
    const uint32_t bTh = sb;              // T hi/lo; becomes pong AC after step 1
    const uint32_t bT2 = sb + 2 * TILE;   // T2 hi (+TILE = lo)
    const uint32_t bP  = sb + 4 * TILE;   // ping AC hi (+TILE = lo)

    const int tid  = threadIdx.x;
    const int warp = tid >> 5;
    const int lane = tid & 31;
    const int row0 = (warp >> 1) * 32;
    const int col0 = (warp & 1) * 32;

    // ---- prologue: T = (M - 3.5 I)/2.5, truncation-split into Th/Tl
    {
        const int pr = tid >> 1, ph = tid & 1;
        const float* gp = gin + (size_t)blockIdx.x * 4096 + pr * 64 + ph * 32;
        float v[32];
#pragma unroll
        for (int j = 0; j < 32; j += 4) {
            const float4 t4 = *reinterpret_cast<const float4*>(gp + j);
            v[j] = t4.x; v[j + 1] = t4.y; v[j + 2] = t4.z; v[j + 3] = t4.w;
        }
        const float inv_beta = 1.0f / 2.5f, alpha = 3.5f;
#pragma unroll
        for (int j = 0; j < 32; ++j)
            v[j] = (v[j] - ((ph * 32 + j == pr) ? alpha : 0.0f)) * inv_beta;

        const uint32_t pmsk = (uint32_t)((pr & 7) << 4);
#pragma unroll
        for (int j = 0; j < 16; ++j) {
            const uint32_t off = ((uint32_t)(pr * 128 + ph * 64 + 4 * j)) ^ pmsk;
            uint32_t h01, l01;
            split_pair(v[2 * j], v[2 * j + 1], h01, l01);
            sts32(bTh + off, h01);
            sts32(bTh + TILE + off, l01);
        }
    }
    __syncthreads();

    // ---- per-thread constant geometry
    const int la = lane & 15, lc = lane >> 4;
    const uint32_t msk = (uint32_t)((la & 7) << 4);
    const uint32_t rX  = (uint32_t)((row0 + la) * 128 + lc * 16);
    const uint32_t rY  = (uint32_t)((col0 + la) * 128 + lc * 16);
    const int er = lane >> 2, ec = (lane & 3) * 2;
    const uint32_t mskE = (uint32_t)((er & 7) << 4);
    const uint32_t rE0  = (uint32_t)((row0 + er) * 128 + (col0 + ec) * 2);

    const uint32_t ownb = (uint32_t)(col0 * 2);         // own k-half byte base
    const uint32_t othb = (uint32_t)((32 - col0) * 2);  // neighbor k-half base

    // T fragments + epilogue offsets + diag masks (registers)
    float2   Treg[16];
    uint32_t eoff[16];
    uint32_t dm0 = 0, dm1 = 0;
#pragma unroll
    for (int mi = 0; mi < 2; ++mi)
#pragma unroll
        for (int ni = 0; ni < 4; ++ni)
#pragma unroll
            for (int hf = 0; hf < 2; ++hf) {
                const int pos = mi * 8 + ni * 2 + hf;
                const uint32_t rel =
                    (rE0 + (uint32_t)(mi * 2048 + ni * 16 + hf * 1024)) ^ mskE;
                eoff[pos] = rel;
                const float2 th = unpackbf(lds32(bTh + rel));
                const float2 tl = unpackbf(lds32(bTh + TILE + rel));
                Treg[pos] = make_float2(th.x + tl.x, th.y + tl.y);
                const int gr = row0 + mi * 16 + er + hf * 8;
                const int gc = col0 + ni * 8 + ec;
                if (gr == gc)     dm0 |= 1u << pos;
                if (gr == gc + 1) dm1 |= 1u << pos;
            }

    float acc[8][4];
    uint32_t xh[2][2][4], xl[2][2][4];     // own-half A-frags [mi][kcl][reg]
    uint32_t ybh[4][2][4], ybl[4][2][4];   // Y (T2) frag cache, by loop slot

    // ================= step 0: X = Y = T =================
#pragma unroll
    for (int t = 0; t < 8; ++t)
#pragma unroll
        for (int e = 0; e < 4; ++e) acc[t][e] = 0.0f;
#pragma unroll
    for (int ks = 0; ks < 4; ++ks) {
        const uint32_t kb = (uint32_t)(ks * 32);
        const uint32_t xa = bTh + ((rX + kb) ^ msk);
        const uint32_t ya = bTh + ((rY + kb) ^ msk);
        uint32_t ah0[4], ah1[4], al0[4], al1[4], bh[2][4], bl[2][4];
        ldsm4(ah0, xa);        ldsm4(ah1, xa + 2048);
        ldsm4(al0, xa + TILE); ldsm4(al1, xa + TILE + 2048);
        ldsm4(bh[0], ya);        ldsm4(bh[1], ya + 2048);
        ldsm4(bl[0], ya + TILE); ldsm4(bl[1], ya + TILE + 2048);
        mma_chunk(acc, ah0, al0, ah1, al1, bh, bl);
    }
    // epilogue 0: T2 = D -> bT2;  AC = a8*D + a7*T + a6*I -> bP + own frags
    {
        const float cd = P.a[8], c1 = P.a[7], cc0 = P.a[6];
#pragma unroll
        for (int mi = 0; mi < 2; ++mi)
#pragma unroll
            for (int ni = 0; ni < 4; ++ni)
#pragma unroll
                for (int hf = 0; hf < 2; ++hf) {
                    const int pos = mi * 8 + ni * 2 + hf;
                    const uint32_t rel = eoff[pos];
                    const float d0 = acc[mi * 4 + ni][2 * hf];
                    const float d1 = acc[mi * 4 + ni][2 * hf + 1];
                    uint32_t t2h, t2l;
                    split_pair(d0, d1, t2h, t2l);
                    sts32(bT2 + rel, t2h);
                    sts32(bT2 + TILE + rel, t2l);
                    float x0 = cd * d0 + c1 * Treg[pos].x;
                    float x1 = cd * d1 + c1 * Treg[pos].y;
                    if ((dm0 >> pos) & 1) x0 += cc0;
                    if ((dm1 >> pos) & 1) x1 += cc0;
                    uint32_t h01, l01;
                    split_pair(x0, x1, h01, l01);
                    sts32(bP + rel, h01);
                    sts32(bP + TILE + rel, l01);
                    xh[mi][ni >> 1][(ni & 1) * 2 + hf] = h01;
                    xl[mi][ni >> 1][(ni & 1) * 2 + hf] = l01;
                }
    }
    __syncthreads();

    // ================= steps 1..3 =================
#pragma unroll
    for (int step = 1; step < 4; ++step) {
        const uint32_t Xo = (step == 2) ? bTh : bP;   // neighbor-half X source
        const uint32_t W  = (step == 1) ? bTh : bP;   // write target (dead @3)
#pragma unroll
        for (int t = 0; t < 8; ++t)
#pragma unroll
            for (int e = 0; e < 4; ++e) acc[t][e] = 0.0f;

        // neighbor-k chunks (slots 0,1): X from smem, Y cached (loaded step 1)
#pragma unroll
        for (int kol = 0; kol < 2; ++kol) {
            const uint32_t kb = othb + (uint32_t)(kol * 32);
            if (step == 1) {
                const uint32_t ya = bT2 + ((rY + kb) ^ msk);
                ldsm4(ybh[kol][0], ya);        ldsm4(ybh[kol][1], ya + 2048);
                ldsm4(ybl[kol][0], ya + TILE); ldsm4(ybl[kol][1], ya + TILE + 2048);
            }
            const uint32_t xa = Xo + ((rX + kb) ^ msk);
            uint32_t ah0[4], ah1[4], al0[4], al1[4];
            ldsm4(ah0, xa);        ldsm4(ah1, xa + 2048);
            ldsm4(al0, xa + TILE); ldsm4(al1, xa + TILE + 2048);
            mma_chunk(acc, ah0, al0, ah1, al1, ybh[kol], ybl[kol]);
        }
        // own-k chunks (slots 2,3): X straight from last epilogue's registers
#pragma unroll
        for (int kcl = 0; kcl < 2; ++kcl) {
            const int slot = 2 + kcl;
            if (step == 1) {
                const uint32_t kb = ownb + (uint32_t)(kcl * 32);
                const uint32_t ya = bT2 + ((rY + kb) ^ msk);
                ldsm4(ybh[slot][0], ya);        ldsm4(ybh[slot][1], ya + 2048);
                ldsm4(ybl[slot][0], ya + TILE); ldsm4(ybl[slot][1], ya + TILE + 2048);
            }
            mma_chunk(acc, xh[0][kcl], xl[0][kcl], xh[1][kcl], xl[1][kcl],
                      ybh[slot], ybl[slot]);
        }

        // epilogue
        float c1, cc0;
        if      (step == 1) { c1 = P.a[5]; cc0 = P.a[4]; }
        else if (step == 2) { c1 = P.a[3]; cc0 = P.a[2]; }
        else                { c1 = P.a[1]; cc0 = P.a[0]; }

#pragma unroll
        for (int mi = 0; mi < 2; ++mi)
#pragma unroll
            for (int ni = 0; ni < 4; ++ni)
#pragma unroll
                for (int hf = 0; hf < 2; ++hf) {
                    const int pos = mi * 8 + ni * 2 + hf;
                    float x0 = acc[mi * 4 + ni][2 * hf]     + c1 * Treg[pos].x;
                    float x1 = acc[mi * 4 + ni][2 * hf + 1] + c1 * Treg[pos].y;
                    if ((dm0 >> pos) & 1) x0 += cc0;
                    if ((dm1 >> pos) & 1) x1 += cc0;
                    if (step < 3) {
                        const uint32_t rel = eoff[pos];
                        uint32_t h01, l01;
                        split_pair(x0, x1, h01, l01);
                        sts32(W + rel, h01);
                        sts32(W + TILE + rel, l01);
                        xh[mi][ni >> 1][(ni & 1) * 2 + hf] = h01;
                        xl[mi][ni >> 1][(ni & 1) * 2 + hf] = l01;
                    } else {
                        const int gr = row0 + mi * 16 + er + hf * 8;
                        const int gc = col0 + ni * 8 + ec;
                        float2* gp = reinterpret_cast<float2*>(
                            gout + (size_t)blockIdx.x * 4096 + gr * 64 + gc);
                        *gp = make_float2(x0, x1);
                    }
                }
        if (step < 3) __syncthreads();
    }
}

extern "C" void kernel_launch(void* const* d_in, const int* in_sizes, int n_in,
                              void* d_out, int out_size) {
    const float* in = (const float*)d_in[0];
    float* out = (float*)d_out;
    const int nmat = in_sizes[0] / 4096;   // 8192 matrices of 64x64

    // Chebyshev coefficients of log on [1,6], converted to monomial basis.
    Poly P;
    {
        const double alpha = 3.5, beta = 2.5;
        const double r = (alpha - sqrt(alpha * alpha - beta * beta)) / beta;
        double c[DEG + 1];
        c[0] = log(alpha / (1.0 + r * r));
        double rk = 1.0;
        for (int k = 1; k <= DEG; ++k) {
            rk *= r;
            c[k] = ((k & 1) ? 2.0 : -2.0) * rk / (double)k;
        }
        double mono[DEG + 1], Tm1[DEG + 1], Tc[DEG + 1], Tn[DEG + 1];
        for (int j = 0; j <= DEG; ++j) { mono[j] = 0; Tm1[j] = 0; Tc[j] = 0; }
        Tm1[0] = 1.0;            // T0
        Tc[1]  = 1.0;            // T1
        for (int j = 0; j <= DEG; ++j) mono[j] = c[0] * Tm1[j] + c[1] * Tc[j];
        for (int k = 2; k <= DEG; ++k) {
            for (int j = 0; j <= DEG; ++j) {
                double t = -Tm1[j];
                if (j > 0) t += 2.0 * Tc[j - 1];
                Tn[j] = t;
            }
            for (int j = 0; j <= DEG; ++j) {
                mono[j] += c[k] * Tn[j];
                Tm1[j] = Tc[j];
                Tc[j]  = Tn[j];
            }
        }
        for (int j = 0; j <= DEG; ++j) P.a[j] = (float)mono[j];
    }

    cudaFuncSetAttribute(logm_hmma_kernel,
                         cudaFuncAttributeMaxDynamicSharedMemorySize, SMEM_TOT);
    logm_hmma_kernel<<<nmat, 128, SMEM_TOT>>>(in, out, P);
}